// round 10
// baseline (speedup 1.0000x reference)
#include <cuda_runtime.h>
#include <cuda_bf16.h>
#include <cuda_fp16.h>
#include <cstdint>
#include <cstddef>

#define DEV_INLINE __device__ __forceinline__

// ---------------- problem dims (fixed) ----------------
#define BATCH_M 8192   // 2*4096 rows of x
#define DIM_K   4096
#define DIM_N   4096

// ---------------- scratch (static device arrays; no cudaMalloc) ----------
__device__ __align__(16) unsigned char g_qx[(size_t)BATCH_M * DIM_K]; // fp8 e4m3, 32 MB
__device__ __align__(16) unsigned char g_qw[(size_t)DIM_N * DIM_K];   // fp8 e4m3, 16 MB
__device__ unsigned int g_amax_bits[2];   // [0]=x, [1]=w
__device__ unsigned int g_lo16_or;        // 0 => x/out are fp32 (bf16-upcast harness mode)

// ---------------- helpers ----------------
DEV_INLINE uint16_t f2_to_e4m3x2(float lo, float hi) {
    // first source operand -> HIGH byte, second -> LOW byte
    uint16_t r;
    asm("cvt.rn.satfinite.e4m3x2.f32 %0, %1, %2;" : "=h"(r) : "f"(hi), "f"(lo));
    return r;
}

// ---------------- reset ----------------
__global__ void init_kernel() {
    if (threadIdx.x == 0) {
        g_amax_bits[0] = 0u; g_amax_bits[1] = 0u; g_lo16_or = 0u;
    }
}

// ---------------- dtype probe (x: fp32-upcast-of-bf16 vs raw bf16) ---------
__global__ void probe_kernel(const unsigned int* __restrict__ xw) {
    unsigned int v = 0;
    const size_t stride = (size_t)65536;
    for (int r = 0; r < 64; r++) v |= xw[r * stride + threadIdx.x] & 0xFFFFu;
    #pragma unroll
    for (int o = 16; o > 0; o >>= 1) v |= __shfl_xor_sync(0xffffffffu, v, o);
    if ((threadIdx.x & 31) == 0 && v) atomicOr(&g_lo16_or, v);
}

// ---------------- amax |x| (dual dtype) ----------------
__global__ void amax_x_kernel(const void* __restrict__ xv) {
    const bool f32mode = (g_lo16_or == 0u);
    float m = 0.0f;
    if (f32mode) {
        const float4* p = reinterpret_cast<const float4*>(xv);
        const int n = (BATCH_M * DIM_K) / 4;
        for (int i = blockIdx.x * blockDim.x + threadIdx.x; i < n; i += gridDim.x * blockDim.x) {
            float4 v = p[i];
            m = fmaxf(m, fabsf(v.x)); m = fmaxf(m, fabsf(v.y));
            m = fmaxf(m, fabsf(v.z)); m = fmaxf(m, fabsf(v.w));
        }
    } else {
        const uint4* p = reinterpret_cast<const uint4*>(xv);
        const int n = (BATCH_M * DIM_K) / 8;
        for (int i = blockIdx.x * blockDim.x + threadIdx.x; i < n; i += gridDim.x * blockDim.x) {
            uint4 v = p[i];
            uint32_t ws[4] = {v.x, v.y, v.z, v.w};
            #pragma unroll
            for (int j = 0; j < 4; j++) {
                __nv_bfloat162 h2 = *reinterpret_cast<__nv_bfloat162*>(&ws[j]);
                m = fmaxf(m, fabsf(__bfloat162float(h2.x)));
                m = fmaxf(m, fabsf(__bfloat162float(h2.y)));
            }
        }
    }
    #pragma unroll
    for (int o = 16; o > 0; o >>= 1) m = fmaxf(m, __shfl_xor_sync(0xffffffffu, m, o));
    if ((threadIdx.x & 31) == 0) atomicMax(&g_amax_bits[0], __float_as_uint(m));
}

// ---------------- amax |w| (fp32) ----------------
__global__ void amax_w_kernel(const float* __restrict__ w) {
    const float4* p = reinterpret_cast<const float4*>(w);
    const int n = (DIM_N * DIM_K) / 4;
    float m = 0.0f;
    for (int i = blockIdx.x * blockDim.x + threadIdx.x; i < n; i += gridDim.x * blockDim.x) {
        float4 v = p[i];
        m = fmaxf(m, fabsf(v.x)); m = fmaxf(m, fabsf(v.y));
        m = fmaxf(m, fabsf(v.z)); m = fmaxf(m, fabsf(v.w));
    }
    #pragma unroll
    for (int o = 16; o > 0; o >>= 1) m = fmaxf(m, __shfl_xor_sync(0xffffffffu, m, o));
    if ((threadIdx.x & 31) == 0) atomicMax(&g_amax_bits[1], __float_as_uint(m));
}

// ---------------- quantize x -> e4m3 bytes (dual dtype) ----------------
__global__ void quant_x_kernel(const void* __restrict__ xv) {
    const bool f32mode = (g_lo16_or == 0u);
    const float amax = __uint_as_float(g_amax_bits[0]);
    const float scale = 448.0f / fmaxf(amax, 1e-12f);
    if (f32mode) {
        const float4* p = reinterpret_cast<const float4*>(xv);
        uint32_t* q = reinterpret_cast<uint32_t*>(g_qx);
        const int n = (BATCH_M * DIM_K) / 4;
        for (int i = blockIdx.x * blockDim.x + threadIdx.x; i < n; i += gridDim.x * blockDim.x) {
            float4 v = p[i];
            q[i] = (uint32_t)f2_to_e4m3x2(v.x * scale, v.y * scale)
                 | ((uint32_t)f2_to_e4m3x2(v.z * scale, v.w * scale) << 16);
        }
    } else {
        const uint4* p = reinterpret_cast<const uint4*>(xv);
        uint2* q = reinterpret_cast<uint2*>(g_qx);
        const int n = (BATCH_M * DIM_K) / 8;
        for (int i = blockIdx.x * blockDim.x + threadIdx.x; i < n; i += gridDim.x * blockDim.x) {
            uint4 v = p[i];
            uint32_t ws[4] = {v.x, v.y, v.z, v.w};
            float f[8];
            #pragma unroll
            for (int j = 0; j < 4; j++) {
                __nv_bfloat162 h2 = *reinterpret_cast<__nv_bfloat162*>(&ws[j]);
                f[2 * j]     = __bfloat162float(h2.x) * scale;
                f[2 * j + 1] = __bfloat162float(h2.y) * scale;
            }
            uint2 o;
            o.x = (uint32_t)f2_to_e4m3x2(f[0], f[1]) | ((uint32_t)f2_to_e4m3x2(f[2], f[3]) << 16);
            o.y = (uint32_t)f2_to_e4m3x2(f[4], f[5]) | ((uint32_t)f2_to_e4m3x2(f[6], f[7]) << 16);
            q[i] = o;
        }
    }
}

// ---------------- quantize w: fp32 -> e4m3 bytes ----------------
__global__ void quant_w_kernel(const float* __restrict__ w) {
    const float amax = __uint_as_float(g_amax_bits[1]);
    const float scale = 448.0f / fmaxf(amax, 1e-12f);
    const float4* p = reinterpret_cast<const float4*>(w);
    uint32_t* q = reinterpret_cast<uint32_t*>(g_qw);
    const int n = (DIM_N * DIM_K) / 4;
    for (int i = blockIdx.x * blockDim.x + threadIdx.x; i < n; i += gridDim.x * blockDim.x) {
        float4 v = p[i];
        q[i] = (uint32_t)f2_to_e4m3x2(v.x * scale, v.y * scale)
             | ((uint32_t)f2_to_e4m3x2(v.z * scale, v.w * scale) << 16);
    }
}

// ======================= GEMM: mma.sync m16n8k32 e4m3 =======================
// C[8192,4096] = qx @ qw^T, both K-major fp8 (row.col TN).
// CTA 128x128x64B, 256 threads, warp tile 64x32, 4-stage cp.async, ldmatrix.

#define BM 128
#define BN 128
#define BK 64                                   // K bytes per chunk
#define GSTAGES 4
#define K_ITERS (DIM_K / BK)                    // 64
#define A_TILE_B (BM * BK)                      // 8192
#define STAGE_BYTES (2 * A_TILE_B)              // 16384
#define SMEM_GEMM (GSTAGES * STAGE_BYTES)       // 65536

// swizzled smem offset for (row, byte) in a [rows][64B] tile
DEV_INLINE uint32_t swzb(uint32_t row, uint32_t byte) {
    return row * 64u + (byte ^ (((row >> 1) & 3u) << 4));
}

DEV_INLINE void cp16(uint32_t dst, const void* src) {
    asm volatile("cp.async.cg.shared.global [%0], [%1], 16;" :: "r"(dst), "l"(src));
}
DEV_INLINE void cp_commit() { asm volatile("cp.async.commit_group;" ::: "memory"); }
DEV_INLINE void cp_wait2()  { asm volatile("cp.async.wait_group 2;" ::: "memory"); }
DEV_INLINE void cp_wait0()  { asm volatile("cp.async.wait_group 0;" ::: "memory"); }

DEV_INLINE void ldsm_x4(uint32_t& r0, uint32_t& r1, uint32_t& r2, uint32_t& r3, uint32_t addr) {
    asm volatile("ldmatrix.sync.aligned.m8n8.x4.shared.b16 {%0,%1,%2,%3}, [%4];"
                 : "=r"(r0), "=r"(r1), "=r"(r2), "=r"(r3) : "r"(addr));
}
DEV_INLINE void ldsm_x2(uint32_t& r0, uint32_t& r1, uint32_t addr) {
    asm volatile("ldmatrix.sync.aligned.m8n8.x2.shared.b16 {%0,%1}, [%2];"
                 : "=r"(r0), "=r"(r1) : "r"(addr));
}

DEV_INLINE void mma_e4m3(float* c, const uint32_t* a, const uint32_t* b) {
    asm volatile(
        "mma.sync.aligned.m16n8k32.row.col.f32.e4m3.e4m3.f32 "
        "{%0,%1,%2,%3}, {%4,%5,%6,%7}, {%8,%9}, {%0,%1,%2,%3};"
        : "+f"(c[0]), "+f"(c[1]), "+f"(c[2]), "+f"(c[3])
        : "r"(a[0]), "r"(a[1]), "r"(a[2]), "r"(a[3]), "r"(b[0]), "r"(b[1]));
}

__global__ void __launch_bounds__(256, 2)
gemm_f8_kernel(const float* __restrict__ bias, void* __restrict__ outv) {
    extern __shared__ __align__(128) char smem_raw[];
    const uint32_t smem0 = (uint32_t)__cvta_generic_to_shared(smem_raw);

    const int tid  = threadIdx.x;
    const int wid  = tid >> 5;
    const int lane = tid & 31;
    const int warpM = (wid & 1) * 64;   // 2 warps over M
    const int warpN = (wid >> 1) * 32;  // 4 warps over N

    const int bx = blockIdx.x;   // N tile (32)
    const int by = blockIdx.y;   // M tile (64)
    const unsigned char* gA = g_qx + (size_t)by * BM * DIM_K;
    const unsigned char* gB = g_qw + (size_t)bx * BN * DIM_K;

    auto load_stage = [&](int s, int kb) {
        const uint32_t base = smem0 + (uint32_t)s * STAGE_BYTES;
        const unsigned char* aSrc = gA + (size_t)kb * BK;
        #pragma unroll
        for (int i = 0; i < 2; i++) {
            int idx = i * 256 + tid;               // 0..511
            uint32_t row = (uint32_t)(idx >> 2), c = (uint32_t)(idx & 3);
            cp16(base + swzb(row, c * 16), aSrc + (size_t)row * DIM_K + c * 16);
        }
        const uint32_t bbase = base + A_TILE_B;
        const unsigned char* bSrc = gB + (size_t)kb * BK;
        #pragma unroll
        for (int i = 0; i < 2; i++) {
            int idx = i * 256 + tid;
            uint32_t row = (uint32_t)(idx >> 2), c = (uint32_t)(idx & 3);
            cp16(bbase + swzb(row, c * 16), bSrc + (size_t)row * DIM_K + c * 16);
        }
    };

    float acc[4][4][4];
    #pragma unroll
    for (int mi = 0; mi < 4; mi++)
        #pragma unroll
        for (int ni = 0; ni < 4; ni++)
            #pragma unroll
            for (int j = 0; j < 4; j++) acc[mi][ni][j] = 0.0f;

    // prologue: 3 stages in flight
    #pragma unroll
    for (int s = 0; s < GSTAGES - 1; s++) { load_stage(s, s); cp_commit(); }

    for (int k = 0; k < K_ITERS; k++) {
        const int s = k & (GSTAGES - 1);
        cp_wait2();           // chunk-k group complete
        __syncthreads();      // all warps done reading the stage being refilled

        const int kn = k + GSTAGES - 1;
        if (kn < K_ITERS) load_stage(kn & (GSTAGES - 1), kn);
        cp_commit();          // exactly one group per iter (accounting)

        const uint32_t aBase = smem0 + (uint32_t)s * STAGE_BYTES;
        const uint32_t bBase = aBase + A_TILE_B;

        #pragma unroll
        for (int ks = 0; ks < 2; ks++) {
            uint32_t af[4][4];
            uint32_t bf[4][2];
            {
                const int mtx = lane >> 3;          // 0..3
                const int r   = lane & 7;
                #pragma unroll
                for (int mi = 0; mi < 4; mi++) {
                    const uint32_t row = (uint32_t)(warpM + mi * 16 + r + ((mtx & 1) << 3));
                    const uint32_t kb  = (uint32_t)((ks * 2 + (mtx >> 1)) * 16);
                    ldsm_x4(af[mi][0], af[mi][1], af[mi][2], af[mi][3], aBase + swzb(row, kb));
                }
                const int bmtx = (lane >> 3) & 1;   // 0..1 (lanes 0..15 feed x2)
                #pragma unroll
                for (int ni = 0; ni < 4; ni++) {
                    const uint32_t row = (uint32_t)(warpN + ni * 8 + r);
                    const uint32_t kb  = (uint32_t)((ks * 2 + bmtx) * 16);
                    ldsm_x2(bf[ni][0], bf[ni][1], bBase + swzb(row, kb));
                }
            }
            #pragma unroll
            for (int mi = 0; mi < 4; mi++)
                #pragma unroll
                for (int ni = 0; ni < 4; ni++)
                    mma_e4m3(acc[mi][ni], af[mi], bf[ni]);
        }
    }
    cp_wait0();  // drain trailing groups

    // ---------------- epilogue: scale, bf16 bias add, dual-dtype store ------
    const float ax = __uint_as_float(g_amax_bits[0]);
    const float aw = __uint_as_float(g_amax_bits[1]);
    const float sc = (1.0f / (448.0f / fmaxf(ax, 1e-12f)))
                   * (1.0f / (448.0f / fmaxf(aw, 1e-12f)));
    const bool f32out = (g_lo16_or == 0u);

    const int colQ = (lane & 3) << 1;            // 0,2,4,6
    __nv_bfloat16 bb[4][2];
    #pragma unroll
    for (int ni = 0; ni < 4; ni++) {
        const int col = bx * BN + warpN + ni * 8 + colQ;
        const float2 bv = *reinterpret_cast<const float2*>(bias + col);
        bb[ni][0] = __float2bfloat16(bv.x);
        bb[ni][1] = __float2bfloat16(bv.y);
    }

    #pragma unroll
    for (int mi = 0; mi < 4; mi++) {
        const size_t row0 = (size_t)(by * BM + warpM + mi * 16 + (lane >> 2));
        #pragma unroll
        for (int ni = 0; ni < 4; ni++) {
            const size_t col = (size_t)(bx * BN + warpN + ni * 8 + colQ);
            __nv_bfloat16 v00 = __hadd(__float2bfloat16(acc[mi][ni][0] * sc), bb[ni][0]);
            __nv_bfloat16 v01 = __hadd(__float2bfloat16(acc[mi][ni][1] * sc), bb[ni][1]);
            __nv_bfloat16 v10 = __hadd(__float2bfloat16(acc[mi][ni][2] * sc), bb[ni][0]);
            __nv_bfloat16 v11 = __hadd(__float2bfloat16(acc[mi][ni][3] * sc), bb[ni][1]);
            if (f32out) {
                float* outp = reinterpret_cast<float*>(outv);
                *reinterpret_cast<float2*>(outp + row0 * DIM_N + col) =
                    make_float2(__bfloat162float(v00), __bfloat162float(v01));
                *reinterpret_cast<float2*>(outp + (row0 + 8) * DIM_N + col) =
                    make_float2(__bfloat162float(v10), __bfloat162float(v11));
            } else {
                __nv_bfloat16* outp = reinterpret_cast<__nv_bfloat16*>(outv);
                __nv_bfloat162 lo = __halves2bfloat162(v00, v01);
                __nv_bfloat162 hi = __halves2bfloat162(v10, v11);
                *reinterpret_cast<uint32_t*>(outp + row0 * DIM_N + col) =
                    *reinterpret_cast<uint32_t*>(&lo);
                *reinterpret_cast<uint32_t*>(outp + (row0 + 8) * DIM_N + col) =
                    *reinterpret_cast<uint32_t*>(&hi);
            }
        }
    }
}

// ---------------- launch ----------------
extern "C" void kernel_launch(void* const* d_in, const int* in_sizes, int n_in,
                              void* d_out, int out_size) {
    const void* x = nullptr;
    const float* w = nullptr;
    const float* bias = nullptr;
    for (int i = 0; i < n_in; i++) {
        if (in_sizes[i] == BATCH_M * DIM_K)      x    = d_in[i];
        else if (in_sizes[i] == DIM_N * DIM_K)   w    = (const float*)d_in[i];
        else if (in_sizes[i] == DIM_N)           bias = (const float*)d_in[i];
    }

    init_kernel<<<1, 32>>>();
    probe_kernel<<<1, 256>>>((const unsigned int*)x);
    amax_x_kernel<<<1024, 256>>>(x);
    amax_w_kernel<<<1024, 256>>>(w);
    quant_x_kernel<<<2048, 256>>>(x);
    quant_w_kernel<<<2048, 256>>>(w);

    cudaFuncSetAttribute(gemm_f8_kernel,
                         cudaFuncAttributeMaxDynamicSharedMemorySize, SMEM_GEMM);
    gemm_f8_kernel<<<dim3(DIM_N / BN, BATCH_M / BM, 1), 256, SMEM_GEMM>>>(bias, d_out);
}

// round 11
// speedup vs baseline: 1.8925x; 1.8925x over previous
#include <cuda_runtime.h>
#include <cuda_bf16.h>
#include <cuda_fp16.h>
#include <cstdint>
#include <cstddef>

#define DEV_INLINE __device__ __forceinline__

// ---------------- problem dims (fixed) ----------------
#define BATCH_M 8192   // 2*4096 rows of x
#define DIM_K   4096
#define DIM_N   4096

// ---------------- scratch (static device arrays; no cudaMalloc) ----------
// quantized values stored as f16 (e4m3 grid is exactly representable in f16)
__device__ __align__(16) __half g_qx_h[(size_t)BATCH_M * DIM_K]; // 64 MB
__device__ __align__(16) __half g_qw_h[(size_t)DIM_N * DIM_K];   // 32 MB
__device__ unsigned int g_amax_bits[2];   // [0]=x, [1]=w
__device__ unsigned int g_lo16_or;        // 0 => x/out are fp32 (bf16-upcast harness mode)

// ---------------- helpers ----------------
// quantize a float pair to e4m3 (RN, satfinite) and return the exact values as f16x2
DEV_INLINE uint32_t qpair_h2(float lo, float hi) {
    uint16_t e;
    asm("cvt.rn.satfinite.e4m3x2.f32 %0, %1, %2;" : "=h"(e) : "f"(hi), "f"(lo));
    uint32_t h;
    asm("cvt.rn.f16x2.e4m3x2 %0, %1;" : "=r"(h) : "h"(e));
    return h;
}

// ---------------- reset ----------------
__global__ void init_kernel() {
    if (threadIdx.x == 0) {
        g_amax_bits[0] = 0u; g_amax_bits[1] = 0u; g_lo16_or = 0u;
    }
}

// ---------------- dtype probe (x: fp32-upcast-of-bf16 vs raw bf16) ---------
__global__ void probe_kernel(const unsigned int* __restrict__ xw) {
    unsigned int v = 0;
    const size_t stride = (size_t)65536;
    for (int r = 0; r < 64; r++) v |= xw[r * stride + threadIdx.x] & 0xFFFFu;
    #pragma unroll
    for (int o = 16; o > 0; o >>= 1) v |= __shfl_xor_sync(0xffffffffu, v, o);
    if ((threadIdx.x & 31) == 0 && v) atomicOr(&g_lo16_or, v);
}

// ---------------- amax |x| (dual dtype) ----------------
__global__ void amax_x_kernel(const void* __restrict__ xv) {
    const bool f32mode = (g_lo16_or == 0u);
    float m = 0.0f;
    if (f32mode) {
        const float4* p = reinterpret_cast<const float4*>(xv);
        const int n = (BATCH_M * DIM_K) / 4;
        for (int i = blockIdx.x * blockDim.x + threadIdx.x; i < n; i += gridDim.x * blockDim.x) {
            float4 v = p[i];
            m = fmaxf(m, fabsf(v.x)); m = fmaxf(m, fabsf(v.y));
            m = fmaxf(m, fabsf(v.z)); m = fmaxf(m, fabsf(v.w));
        }
    } else {
        const uint4* p = reinterpret_cast<const uint4*>(xv);
        const int n = (BATCH_M * DIM_K) / 8;
        for (int i = blockIdx.x * blockDim.x + threadIdx.x; i < n; i += gridDim.x * blockDim.x) {
            uint4 v = p[i];
            uint32_t ws[4] = {v.x, v.y, v.z, v.w};
            #pragma unroll
            for (int j = 0; j < 4; j++) {
                __nv_bfloat162 h2 = *reinterpret_cast<__nv_bfloat162*>(&ws[j]);
                m = fmaxf(m, fabsf(__bfloat162float(h2.x)));
                m = fmaxf(m, fabsf(__bfloat162float(h2.y)));
            }
        }
    }
    #pragma unroll
    for (int o = 16; o > 0; o >>= 1) m = fmaxf(m, __shfl_xor_sync(0xffffffffu, m, o));
    if ((threadIdx.x & 31) == 0) atomicMax(&g_amax_bits[0], __float_as_uint(m));
}

// ---------------- amax |w| (fp32) ----------------
__global__ void amax_w_kernel(const float* __restrict__ w) {
    const float4* p = reinterpret_cast<const float4*>(w);
    const int n = (DIM_N * DIM_K) / 4;
    float m = 0.0f;
    for (int i = blockIdx.x * blockDim.x + threadIdx.x; i < n; i += gridDim.x * blockDim.x) {
        float4 v = p[i];
        m = fmaxf(m, fabsf(v.x)); m = fmaxf(m, fabsf(v.y));
        m = fmaxf(m, fabsf(v.z)); m = fmaxf(m, fabsf(v.w));
    }
    #pragma unroll
    for (int o = 16; o > 0; o >>= 1) m = fmaxf(m, __shfl_xor_sync(0xffffffffu, m, o));
    if ((threadIdx.x & 31) == 0) atomicMax(&g_amax_bits[1], __float_as_uint(m));
}

// ---------------- quantize x -> e4m3 grid (stored as f16), dual dtype ------
__global__ void quant_x_kernel(const void* __restrict__ xv) {
    const bool f32mode = (g_lo16_or == 0u);
    const float amax = __uint_as_float(g_amax_bits[0]);
    const float scale = 448.0f / fmaxf(amax, 1e-12f);
    if (f32mode) {
        const float4* p = reinterpret_cast<const float4*>(xv);
        uint2* q = reinterpret_cast<uint2*>(g_qx_h);
        const int n = (BATCH_M * DIM_K) / 4;
        for (int i = blockIdx.x * blockDim.x + threadIdx.x; i < n; i += gridDim.x * blockDim.x) {
            float4 v = p[i];
            uint2 o;
            o.x = qpair_h2(v.x * scale, v.y * scale);
            o.y = qpair_h2(v.z * scale, v.w * scale);
            q[i] = o;
        }
    } else {
        const uint4* p = reinterpret_cast<const uint4*>(xv);
        uint4* q = reinterpret_cast<uint4*>(g_qx_h);
        const int n = (BATCH_M * DIM_K) / 8;
        for (int i = blockIdx.x * blockDim.x + threadIdx.x; i < n; i += gridDim.x * blockDim.x) {
            uint4 v = p[i];
            uint32_t ws[4] = {v.x, v.y, v.z, v.w};
            uint4 o;
            uint32_t* op = reinterpret_cast<uint32_t*>(&o);
            #pragma unroll
            for (int j = 0; j < 4; j++) {
                __nv_bfloat162 h2 = *reinterpret_cast<__nv_bfloat162*>(&ws[j]);
                op[j] = qpair_h2(__bfloat162float(h2.x) * scale,
                                 __bfloat162float(h2.y) * scale);
            }
            q[i] = o;
        }
    }
}

// ---------------- quantize w: fp32 -> e4m3 grid (stored as f16) -------------
__global__ void quant_w_kernel(const float* __restrict__ w) {
    const float amax = __uint_as_float(g_amax_bits[1]);
    const float scale = 448.0f / fmaxf(amax, 1e-12f);
    const float4* p = reinterpret_cast<const float4*>(w);
    uint2* q = reinterpret_cast<uint2*>(g_qw_h);
    const int n = (DIM_N * DIM_K) / 4;
    for (int i = blockIdx.x * blockDim.x + threadIdx.x; i < n; i += gridDim.x * blockDim.x) {
        float4 v = p[i];
        uint2 o;
        o.x = qpair_h2(v.x * scale, v.y * scale);
        o.y = qpair_h2(v.z * scale, v.w * scale);
        q[i] = o;
    }
}

// ======================= GEMM: mma.sync m16n8k16 f16 + ldmatrix ============
// C[8192,4096] = qx @ qw^T, both K-major f16 (row.col TN).
// CTA 128x128x64(f16), 256 threads, warp tile 64x32, 3-stage cp.async.

#define BM 128
#define BN 128
#define BK 64                                    // f16 elements -> 128B per row
#define GSTAGES 3
#define K_ITERS (DIM_K / BK)                     // 64
#define A_TILE_B (BM * BK * 2)                   // 16384
#define STAGE_BYTES (2 * A_TILE_B)               // 32768 (A + B)
#define SMEM_GEMM (GSTAGES * STAGE_BYTES)        // 98304

// swizzle within a [rows][128B] tile: XOR 16B-chunk index (3 bits) with row&7
DEV_INLINE uint32_t swzh(uint32_t row, uint32_t byte) {
    return row * 128u + ((((byte >> 4) ^ (row & 7u)) << 4) | (byte & 15u));
}

DEV_INLINE void cp16(uint32_t dst, const void* src) {
    asm volatile("cp.async.cg.shared.global [%0], [%1], 16;" :: "r"(dst), "l"(src));
}
DEV_INLINE void cp_commit() { asm volatile("cp.async.commit_group;" ::: "memory"); }
DEV_INLINE void cp_wait1()  { asm volatile("cp.async.wait_group 1;" ::: "memory"); }
DEV_INLINE void cp_wait0()  { asm volatile("cp.async.wait_group 0;" ::: "memory"); }

DEV_INLINE void ldsm_x4(uint32_t& r0, uint32_t& r1, uint32_t& r2, uint32_t& r3, uint32_t addr) {
    asm volatile("ldmatrix.sync.aligned.m8n8.x4.shared.b16 {%0,%1,%2,%3}, [%4];"
                 : "=r"(r0), "=r"(r1), "=r"(r2), "=r"(r3) : "r"(addr));
}

DEV_INLINE void mma_f16(float* c, const uint32_t* a, const uint32_t* b) {
    asm volatile(
        "mma.sync.aligned.m16n8k16.row.col.f32.f16.f16.f32 "
        "{%0,%1,%2,%3}, {%4,%5,%6,%7}, {%8,%9}, {%0,%1,%2,%3};"
        : "+f"(c[0]), "+f"(c[1]), "+f"(c[2]), "+f"(c[3])
        : "r"(a[0]), "r"(a[1]), "r"(a[2]), "r"(a[3]), "r"(b[0]), "r"(b[1]));
}

__global__ void __launch_bounds__(256, 2)
gemm_f16_kernel(const float* __restrict__ bias, void* __restrict__ outv) {
    extern __shared__ __align__(128) char smem_raw[];
    const uint32_t smem0 = (uint32_t)__cvta_generic_to_shared(smem_raw);

    const int tid  = threadIdx.x;
    const int wid  = tid >> 5;
    const int lane = tid & 31;
    const int warpM = (wid & 1) * 64;   // 2 warps over M
    const int warpN = (wid >> 1) * 32;  // 4 warps over N

    // ldmatrix.x4 lane->address components
    const uint32_t aRowOff  = (uint32_t)((lane & 7) + ((lane >> 3) & 1) * 8);
    const uint32_t aByteOff = (uint32_t)((lane >> 4) * 16);
    const uint32_t bRowOff  = (uint32_t)((lane & 7) + (lane >> 4) * 8);
    const uint32_t bByteOff = (uint32_t)(((lane >> 3) & 1) * 16);

    const int bx = blockIdx.x;   // N tile (32)
    const int by = blockIdx.y;   // M tile (64)
    const __half* gA = g_qx_h + (size_t)by * BM * DIM_K;
    const __half* gB = g_qw_h + (size_t)bx * BN * DIM_K;

    auto load_stage = [&](int s, int kb) {
        const uint32_t base = smem0 + (uint32_t)s * STAGE_BYTES;
        const __half* aSrc = gA + (size_t)kb * BK;
        #pragma unroll
        for (int i = 0; i < 4; i++) {
            int idx = i * 256 + tid;               // 0..1023
            uint32_t row = (uint32_t)(idx >> 3), c = (uint32_t)(idx & 7);
            cp16(base + row * 128u + ((c ^ (row & 7u)) << 4),
                 aSrc + (size_t)row * DIM_K + c * 8);
        }
        const uint32_t bbase = base + A_TILE_B;
        const __half* bSrc = gB + (size_t)kb * BK;
        #pragma unroll
        for (int i = 0; i < 4; i++) {
            int idx = i * 256 + tid;
            uint32_t row = (uint32_t)(idx >> 3), c = (uint32_t)(idx & 7);
            cp16(bbase + row * 128u + ((c ^ (row & 7u)) << 4),
                 bSrc + (size_t)row * DIM_K + c * 8);
        }
    };

    float acc[4][4][4];
    #pragma unroll
    for (int mi = 0; mi < 4; mi++)
        #pragma unroll
        for (int ni = 0; ni < 4; ni++)
            #pragma unroll
            for (int j = 0; j < 4; j++) acc[mi][ni][j] = 0.0f;

    // prologue: 2 stages in flight
    load_stage(0, 0); cp_commit();
    load_stage(1, 1); cp_commit();

    int sC = 0;       // stage holding chunk k
    int sL = 2;       // stage to load chunk k+2 into
    for (int k = 0; k < K_ITERS; k++) {
        cp_wait1();           // chunk-k group complete
        __syncthreads();      // all warps done reading the stage being refilled

        const int kn = k + 2;
        if (kn < K_ITERS) load_stage(sL, kn);
        cp_commit();          // exactly one group per iter (accounting)

        const uint32_t aBase = smem0 + (uint32_t)sC * STAGE_BYTES;
        const uint32_t bBase = aBase + A_TILE_B;

        #pragma unroll
        for (int ks = 0; ks < 4; ks++) {
            const uint32_t kb = (uint32_t)(ks * 32);
            uint32_t af[4][4];
            uint32_t bf[4][2];
            #pragma unroll
            for (int mi = 0; mi < 4; mi++) {
                const uint32_t row = (uint32_t)(warpM + mi * 16) + aRowOff;
                ldsm_x4(af[mi][0], af[mi][1], af[mi][2], af[mi][3],
                        aBase + swzh(row, kb + aByteOff));
            }
            #pragma unroll
            for (int np = 0; np < 2; np++) {
                const uint32_t row = (uint32_t)(warpN + np * 16) + bRowOff;
                ldsm_x4(bf[2 * np][0], bf[2 * np][1], bf[2 * np + 1][0], bf[2 * np + 1][1],
                        bBase + swzh(row, kb + bByteOff));
            }
            #pragma unroll
            for (int mi = 0; mi < 4; mi++)
                #pragma unroll
                for (int ni = 0; ni < 4; ni++)
                    mma_f16(acc[mi][ni], af[mi], bf[ni]);
        }

        sC = (sC == GSTAGES - 1) ? 0 : sC + 1;
        sL = (sL == GSTAGES - 1) ? 0 : sL + 1;
    }
    cp_wait0();  // drain trailing (possibly empty) groups

    // ---------------- epilogue: scale, bf16 bias add, dual-dtype store ------
    const float ax = __uint_as_float(g_amax_bits[0]);
    const float aw = __uint_as_float(g_amax_bits[1]);
    const float sc = (1.0f / (448.0f / fmaxf(ax, 1e-12f)))
                   * (1.0f / (448.0f / fmaxf(aw, 1e-12f)));
    const bool f32out = (g_lo16_or == 0u);

    const int colQ = (lane & 3) << 1;            // 0,2,4,6
    __nv_bfloat16 bb[4][2];
    #pragma unroll
    for (int ni = 0; ni < 4; ni++) {
        const int col = bx * BN + warpN + ni * 8 + colQ;
        const float2 bv = *reinterpret_cast<const float2*>(bias + col);
        bb[ni][0] = __float2bfloat16(bv.x);
        bb[ni][1] = __float2bfloat16(bv.y);
    }

    #pragma unroll
    for (int mi = 0; mi < 4; mi++) {
        const size_t row0 = (size_t)(by * BM + warpM + mi * 16 + (lane >> 2));
        #pragma unroll
        for (int ni = 0; ni < 4; ni++) {
            const size_t col = (size_t)(bx * BN + warpN + ni * 8 + colQ);
            __nv_bfloat16 v00 = __hadd(__float2bfloat16(acc[mi][ni][0] * sc), bb[ni][0]);
            __nv_bfloat16 v01 = __hadd(__float2bfloat16(acc[mi][ni][1] * sc), bb[ni][1]);
            __nv_bfloat16 v10 = __hadd(__float2bfloat16(acc[mi][ni][2] * sc), bb[ni][0]);
            __nv_bfloat16 v11 = __hadd(__float2bfloat16(acc[mi][ni][3] * sc), bb[ni][1]);
            if (f32out) {
                float* outp = reinterpret_cast<float*>(outv);
                *reinterpret_cast<float2*>(outp + row0 * DIM_N + col) =
                    make_float2(__bfloat162float(v00), __bfloat162float(v01));
                *reinterpret_cast<float2*>(outp + (row0 + 8) * DIM_N + col) =
                    make_float2(__bfloat162float(v10), __bfloat162float(v11));
            } else {
                __nv_bfloat16* outp = reinterpret_cast<__nv_bfloat16*>(outv);
                __nv_bfloat162 lo = __halves2bfloat162(v00, v01);
                __nv_bfloat162 hi = __halves2bfloat162(v10, v11);
                *reinterpret_cast<uint32_t*>(outp + row0 * DIM_N + col) =
                    *reinterpret_cast<uint32_t*>(&lo);
                *reinterpret_cast<uint32_t*>(outp + (row0 + 8) * DIM_N + col) =
                    *reinterpret_cast<uint32_t*>(&hi);
            }
        }
    }
}

// ---------------- launch ----------------
extern "C" void kernel_launch(void* const* d_in, const int* in_sizes, int n_in,
                              void* d_out, int out_size) {
    const void* x = nullptr;
    const float* w = nullptr;
    const float* bias = nullptr;
    for (int i = 0; i < n_in; i++) {
        if (in_sizes[i] == BATCH_M * DIM_K)      x    = d_in[i];
        else if (in_sizes[i] == DIM_N * DIM_K)   w    = (const float*)d_in[i];
        else if (in_sizes[i] == DIM_N)           bias = (const float*)d_in[i];
    }

    init_kernel<<<1, 32>>>();
    probe_kernel<<<1, 256>>>((const unsigned int*)x);
    amax_x_kernel<<<1024, 256>>>(x);
    amax_w_kernel<<<1024, 256>>>(w);
    quant_x_kernel<<<2048, 256>>>(x);
    quant_w_kernel<<<2048, 256>>>(w);

    cudaFuncSetAttribute(gemm_f16_kernel,
                         cudaFuncAttributeMaxDynamicSharedMemorySize, SMEM_GEMM);
    gemm_f16_kernel<<<dim3(DIM_N / BN, BATCH_M / BM, 1), 256, SMEM_GEMM>>>(bias, d_out);
}

// round 14
// speedup vs baseline: 1.9072x; 1.0078x over previous
#include <cuda_runtime.h>
#include <cuda_bf16.h>
#include <cuda_fp16.h>
#include <cstdint>
#include <cstddef>

#define DEV_INLINE __device__ __forceinline__

// ---------------- problem dims (fixed) ----------------
#define BATCH_M 8192   // 2*4096 rows of x
#define DIM_K   4096
#define DIM_N   4096

// ---------------- scratch (static device arrays; no cudaMalloc) ----------
// quantized values stored as f16 (e4m3 grid is exactly representable in f16)
__device__ __align__(16) __half g_qx_h[(size_t)BATCH_M * DIM_K]; // 64 MB
__device__ __align__(16) __half g_qw_h[(size_t)DIM_N * DIM_K];   // 32 MB
__device__ unsigned int g_amax_bits[2];   // [0]=x, [1]=w
__device__ unsigned int g_lo16_or;        // 0 => x/out are fp32 (bf16-upcast harness mode)

// ---------------- helpers ----------------
DEV_INLINE uint32_t qpair_h2(float lo, float hi) {
    uint16_t e;
    asm("cvt.rn.satfinite.e4m3x2.f32 %0, %1, %2;" : "=h"(e) : "f"(hi), "f"(lo));
    uint32_t h;
    asm("cvt.rn.f16x2.e4m3x2 %0, %1;" : "=r"(h) : "h"(e));
    return h;
}

DEV_INLINE float fmax4abs(float4 v, float m) {
    m = fmaxf(m, fabsf(v.x)); m = fmaxf(m, fabsf(v.y));
    m = fmaxf(m, fabsf(v.z)); m = fmaxf(m, fabsf(v.w));
    return m;
}

// ---------------- probe (also resets globals; single block) ----------------
__global__ void probe_kernel(const unsigned int* __restrict__ xw) {
    if (threadIdx.x == 0) {
        g_amax_bits[0] = 0u; g_amax_bits[1] = 0u; g_lo16_or = 0u;
    }
    __syncthreads();
    unsigned int v = 0;
    const size_t stride = (size_t)65536;
    for (int r = 0; r < 64; r++) v |= xw[r * stride + threadIdx.x] & 0xFFFFu;
    #pragma unroll
    for (int o = 16; o > 0; o >>= 1) v |= __shfl_xor_sync(0xffffffffu, v, o);
    if ((threadIdx.x & 31) == 0 && v) atomicOr(&g_lo16_or, v);
}

// ---------------- amax |x| (dual dtype, MLP=4) ----------------
__global__ void amax_x_kernel(const void* __restrict__ xv) {
    const bool f32mode = (g_lo16_or == 0u);
    const int S = gridDim.x * blockDim.x;
    const int base = blockIdx.x * blockDim.x + threadIdx.x;
    float m = 0.0f;
    if (f32mode) {
        const float4* p = reinterpret_cast<const float4*>(xv);
        const int n = (BATCH_M * DIM_K) / 4;          // 8388608
        for (int i = base; i < n; i += 4 * S) {       // n divisible by 4*S
            float4 v0 = p[i];
            float4 v1 = p[i + S];
            float4 v2 = p[i + 2 * S];
            float4 v3 = p[i + 3 * S];
            m = fmax4abs(v0, m); m = fmax4abs(v1, m);
            m = fmax4abs(v2, m); m = fmax4abs(v3, m);
        }
    } else {
        const uint4* p = reinterpret_cast<const uint4*>(xv);
        const int n = (BATCH_M * DIM_K) / 8;
        for (int i = base; i < n; i += S) {
            uint4 v = p[i];
            uint32_t ws[4] = {v.x, v.y, v.z, v.w};
            #pragma unroll
            for (int j = 0; j < 4; j++) {
                __nv_bfloat162 h2 = *reinterpret_cast<__nv_bfloat162*>(&ws[j]);
                m = fmaxf(m, fabsf(__bfloat162float(h2.x)));
                m = fmaxf(m, fabsf(__bfloat162float(h2.y)));
            }
        }
    }
    #pragma unroll
    for (int o = 16; o > 0; o >>= 1) m = fmaxf(m, __shfl_xor_sync(0xffffffffu, m, o));
    if ((threadIdx.x & 31) == 0) atomicMax(&g_amax_bits[0], __float_as_uint(m));
}

// ---------------- amax |w| (fp32, MLP=4) ----------------
__global__ void amax_w_kernel(const float* __restrict__ w) {
    const float4* p = reinterpret_cast<const float4*>(w);
    const int n = (DIM_N * DIM_K) / 4;                // 4194304
    const int S = gridDim.x * blockDim.x;
    const int base = blockIdx.x * blockDim.x + threadIdx.x;
    float m = 0.0f;
    for (int i = base; i < n; i += 4 * S) {           // n divisible by 4*S
        float4 v0 = p[i];
        float4 v1 = p[i + S];
        float4 v2 = p[i + 2 * S];
        float4 v3 = p[i + 3 * S];
        m = fmax4abs(v0, m); m = fmax4abs(v1, m);
        m = fmax4abs(v2, m); m = fmax4abs(v3, m);
    }
    #pragma unroll
    for (int o = 16; o > 0; o >>= 1) m = fmaxf(m, __shfl_xor_sync(0xffffffffu, m, o));
    if ((threadIdx.x & 31) == 0) atomicMax(&g_amax_bits[1], __float_as_uint(m));
}

// ---------------- quantize x -> e4m3 grid (stored as f16), MLP=4 ----------
__global__ void quant_x_kernel(const void* __restrict__ xv) {
    const bool f32mode = (g_lo16_or == 0u);
    const float amax = __uint_as_float(g_amax_bits[0]);
    const float scale = 448.0f / fmaxf(amax, 1e-12f);
    const int S = gridDim.x * blockDim.x;
    const int base = blockIdx.x * blockDim.x + threadIdx.x;
    if (f32mode) {
        const float4* p = reinterpret_cast<const float4*>(xv);
        uint2* q = reinterpret_cast<uint2*>(g_qx_h);
        const int n = (BATCH_M * DIM_K) / 4;          // 8388608
        for (int i = base; i < n; i += 4 * S) {
            float4 v0 = p[i];
            float4 v1 = p[i + S];
            float4 v2 = p[i + 2 * S];
            float4 v3 = p[i + 3 * S];
            q[i]         = make_uint2(qpair_h2(v0.x * scale, v0.y * scale),
                                      qpair_h2(v0.z * scale, v0.w * scale));
            q[i + S]     = make_uint2(qpair_h2(v1.x * scale, v1.y * scale),
                                      qpair_h2(v1.z * scale, v1.w * scale));
            q[i + 2 * S] = make_uint2(qpair_h2(v2.x * scale, v2.y * scale),
                                      qpair_h2(v2.z * scale, v2.w * scale));
            q[i + 3 * S] = make_uint2(qpair_h2(v3.x * scale, v3.y * scale),
                                      qpair_h2(v3.z * scale, v3.w * scale));
        }
    } else {
        const uint4* p = reinterpret_cast<const uint4*>(xv);
        uint4* q = reinterpret_cast<uint4*>(g_qx_h);
        const int n = (BATCH_M * DIM_K) / 8;
        for (int i = base; i < n; i += S) {
            uint4 v = p[i];
            uint32_t ws[4] = {v.x, v.y, v.z, v.w};
            uint4 o;
            uint32_t* op = reinterpret_cast<uint32_t*>(&o);
            #pragma unroll
            for (int j = 0; j < 4; j++) {
                __nv_bfloat162 h2 = *reinterpret_cast<__nv_bfloat162*>(&ws[j]);
                op[j] = qpair_h2(__bfloat162float(h2.x) * scale,
                                 __bfloat162float(h2.y) * scale);
            }
            q[i] = o;
        }
    }
}

// ---------------- quantize w: fp32 -> e4m3 grid (stored as f16), MLP=4 -----
__global__ void quant_w_kernel(const float* __restrict__ w) {
    const float amax = __uint_as_float(g_amax_bits[1]);
    const float scale = 448.0f / fmaxf(amax, 1e-12f);
    const float4* p = reinterpret_cast<const float4*>(w);
    uint2* q = reinterpret_cast<uint2*>(g_qw_h);
    const int n = (DIM_N * DIM_K) / 4;                // 4194304
    const int S = gridDim.x * blockDim.x;
    const int base = blockIdx.x * blockDim.x + threadIdx.x;
    for (int i = base; i < n; i += 4 * S) {
        float4 v0 = p[i];
        float4 v1 = p[i + S];
        float4 v2 = p[i + 2 * S];
        float4 v3 = p[i + 3 * S];
        q[i]         = make_uint2(qpair_h2(v0.x * scale, v0.y * scale),
                                  qpair_h2(v0.z * scale, v0.w * scale));
        q[i + S]     = make_uint2(qpair_h2(v1.x * scale, v1.y * scale),
                                  qpair_h2(v1.z * scale, v1.w * scale));
        q[i + 2 * S] = make_uint2(qpair_h2(v2.x * scale, v2.y * scale),
                                  qpair_h2(v2.z * scale, v2.w * scale));
        q[i + 3 * S] = make_uint2(qpair_h2(v3.x * scale, v3.y * scale),
                                  qpair_h2(v3.z * scale, v3.w * scale));
    }
}

// ======================= GEMM: mma.sync m16n8k16 f16 + ldmatrix ============
// (unchanged from R11 — measured at ~the legacy HMMA issue ceiling)

#define BM 128
#define BN 128
#define BK 64
#define GSTAGES 3
#define K_ITERS (DIM_K / BK)                     // 64
#define A_TILE_B (BM * BK * 2)                   // 16384
#define STAGE_BYTES (2 * A_TILE_B)               // 32768
#define SMEM_GEMM (GSTAGES * STAGE_BYTES)        // 98304

DEV_INLINE uint32_t swzh(uint32_t row, uint32_t byte) {
    return row * 128u + ((((byte >> 4) ^ (row & 7u)) << 4) | (byte & 15u));
}

DEV_INLINE void cp16(uint32_t dst, const void* src) {
    asm volatile("cp.async.cg.shared.global [%0], [%1], 16;" :: "r"(dst), "l"(src));
}
DEV_INLINE void cp_commit() { asm volatile("cp.async.commit_group;" ::: "memory"); }
DEV_INLINE void cp_wait1()  { asm volatile("cp.async.wait_group 1;" ::: "memory"); }
DEV_INLINE void cp_wait0()  { asm volatile("cp.async.wait_group 0;" ::: "memory"); }

DEV_INLINE void ldsm_x4(uint32_t& r0, uint32_t& r1, uint32_t& r2, uint32_t& r3, uint32_t addr) {
    asm volatile("ldmatrix.sync.aligned.m8n8.x4.shared.b16 {%0,%1,%2,%3}, [%4];"
                 : "=r"(r0), "=r"(r1), "=r"(r2), "=r"(r3) : "r"(addr));
}

DEV_INLINE void mma_f16(float* c, const uint32_t* a, const uint32_t* b) {
    asm volatile(
        "mma.sync.aligned.m16n8k16.row.col.f32.f16.f16.f32 "
        "{%0,%1,%2,%3}, {%4,%5,%6,%7}, {%8,%9}, {%0,%1,%2,%3};"
        : "+f"(c[0]), "+f"(c[1]), "+f"(c[2]), "+f"(c[3])
        : "r"(a[0]), "r"(a[1]), "r"(a[2]), "r"(a[3]), "r"(b[0]), "r"(b[1]));
}

__global__ void __launch_bounds__(256, 2)
gemm_f16_kernel(const float* __restrict__ bias, void* __restrict__ outv) {
    extern __shared__ __align__(128) char smem_raw[];
    const uint32_t smem0 = (uint32_t)__cvta_generic_to_shared(smem_raw);

    const int tid  = threadIdx.x;
    const int wid  = tid >> 5;
    const int lane = tid & 31;
    const int warpM = (wid & 1) * 64;
    const int warpN = (wid >> 1) * 32;

    const uint32_t aRowOff  = (uint32_t)((lane & 7) + ((lane >> 3) & 1) * 8);
    const uint32_t aByteOff = (uint32_t)((lane >> 4) * 16);
    const uint32_t bRowOff  = (uint32_t)((lane & 7) + (lane >> 4) * 8);
    const uint32_t bByteOff = (uint32_t)(((lane >> 3) & 1) * 16);

    const int bx = blockIdx.x;
    const int by = blockIdx.y;
    const __half* gA = g_qx_h + (size_t)by * BM * DIM_K;
    const __half* gB = g_qw_h + (size_t)bx * BN * DIM_K;

    auto load_stage = [&](int s, int kb) {
        const uint32_t base = smem0 + (uint32_t)s * STAGE_BYTES;
        const __half* aSrc = gA + (size_t)kb * BK;
        #pragma unroll
        for (int i = 0; i < 4; i++) {
            int idx = i * 256 + tid;
            uint32_t row = (uint32_t)(idx >> 3), c = (uint32_t)(idx & 7);
            cp16(base + row * 128u + ((c ^ (row & 7u)) << 4),
                 aSrc + (size_t)row * DIM_K + c * 8);
        }
        const uint32_t bbase = base + A_TILE_B;
        const __half* bSrc = gB + (size_t)kb * BK;
        #pragma unroll
        for (int i = 0; i < 4; i++) {
            int idx = i * 256 + tid;
            uint32_t row = (uint32_t)(idx >> 3), c = (uint32_t)(idx & 7);
            cp16(bbase + row * 128u + ((c ^ (row & 7u)) << 4),
                 bSrc + (size_t)row * DIM_K + c * 8);
        }
    };

    float acc[4][4][4];
    #pragma unroll
    for (int mi = 0; mi < 4; mi++)
        #pragma unroll
        for (int ni = 0; ni < 4; ni++)
            #pragma unroll
            for (int j = 0; j < 4; j++) acc[mi][ni][j] = 0.0f;

    load_stage(0, 0); cp_commit();
    load_stage(1, 1); cp_commit();

    int sC = 0;
    int sL = 2;
    for (int k = 0; k < K_ITERS; k++) {
        cp_wait1();
        __syncthreads();

        const int kn = k + 2;
        if (kn < K_ITERS) load_stage(sL, kn);
        cp_commit();

        const uint32_t aBase = smem0 + (uint32_t)sC * STAGE_BYTES;
        const uint32_t bBase = aBase + A_TILE_B;

        #pragma unroll
        for (int ks = 0; ks < 4; ks++) {
            const uint32_t kb = (uint32_t)(ks * 32);
            uint32_t af[4][4];
            uint32_t bf[4][2];
            #pragma unroll
            for (int mi = 0; mi < 4; mi++) {
                const uint32_t row = (uint32_t)(warpM + mi * 16) + aRowOff;
                ldsm_x4(af[mi][0], af[mi][1], af[mi][2], af[mi][3],
                        aBase + swzh(row, kb + aByteOff));
            }
            #pragma unroll
            for (int np = 0; np < 2; np++) {
                const uint32_t row = (uint32_t)(warpN + np * 16) + bRowOff;
                ldsm_x4(bf[2 * np][0], bf[2 * np][1], bf[2 * np + 1][0], bf[2 * np + 1][1],
                        bBase + swzh(row, kb + bByteOff));
            }
            #pragma unroll
            for (int mi = 0; mi < 4; mi++)
                #pragma unroll
                for (int ni = 0; ni < 4; ni++)
                    mma_f16(acc[mi][ni], af[mi], bf[ni]);
        }

        sC = (sC == GSTAGES - 1) ? 0 : sC + 1;
        sL = (sL == GSTAGES - 1) ? 0 : sL + 1;
    }
    cp_wait0();

    // ---------------- epilogue: scale, bf16 bias add, dual-dtype store ------
    const float ax = __uint_as_float(g_amax_bits[0]);
    const float aw = __uint_as_float(g_amax_bits[1]);
    const float sc = (1.0f / (448.0f / fmaxf(ax, 1e-12f)))
                   * (1.0f / (448.0f / fmaxf(aw, 1e-12f)));
    const bool f32out = (g_lo16_or == 0u);

    const int colQ = (lane & 3) << 1;
    __nv_bfloat16 bb[4][2];
    #pragma unroll
    for (int ni = 0; ni < 4; ni++) {
        const int col = bx * BN + warpN + ni * 8 + colQ;
        const float2 bv = *reinterpret_cast<const float2*>(bias + col);
        bb[ni][0] = __float2bfloat16(bv.x);
        bb[ni][1] = __float2bfloat16(bv.y);
    }

    #pragma unroll
    for (int mi = 0; mi < 4; mi++) {
        const size_t row0 = (size_t)(by * BM + warpM + mi * 16 + (lane >> 2));
        #pragma unroll
        for (int ni = 0; ni < 4; ni++) {
            const size_t col = (size_t)(bx * BN + warpN + ni * 8 + colQ);
            __nv_bfloat16 v00 = __hadd(__float2bfloat16(acc[mi][ni][0] * sc), bb[ni][0]);
            __nv_bfloat16 v01 = __hadd(__float2bfloat16(acc[mi][ni][1] * sc), bb[ni][1]);
            __nv_bfloat16 v10 = __hadd(__float2bfloat16(acc[mi][ni][2] * sc), bb[ni][0]);
            __nv_bfloat16 v11 = __hadd(__float2bfloat16(acc[mi][ni][3] * sc), bb[ni][1]);
            if (f32out) {
                float* outp = reinterpret_cast<float*>(outv);
                *reinterpret_cast<float2*>(outp + row0 * DIM_N + col) =
                    make_float2(__bfloat162float(v00), __bfloat162float(v01));
                *reinterpret_cast<float2*>(outp + (row0 + 8) * DIM_N + col) =
                    make_float2(__bfloat162float(v10), __bfloat162float(v11));
            } else {
                __nv_bfloat16* outp = reinterpret_cast<__nv_bfloat16*>(outv);
                __nv_bfloat162 lo = __halves2bfloat162(v00, v01);
                __nv_bfloat162 hi = __halves2bfloat162(v10, v11);
                *reinterpret_cast<uint32_t*>(outp + row0 * DIM_N + col) =
                    *reinterpret_cast<uint32_t*>(&lo);
                *reinterpret_cast<uint32_t*>(outp + (row0 + 8) * DIM_N + col) =
                    *reinterpret_cast<uint32_t*>(&hi);
            }
        }
    }
}

// ---------------- launch ----------------
extern "C" void kernel_launch(void* const* d_in, const int* in_sizes, int n_in,
                              void* d_out, int out_size) {
    const void* x = nullptr;
    const float* w = nullptr;
    const float* bias = nullptr;
    for (int i = 0; i < n_in; i++) {
        if (in_sizes[i] == BATCH_M * DIM_K)      x    = d_in[i];
        else if (in_sizes[i] == DIM_N * DIM_K)   w    = (const float*)d_in[i];
        else if (in_sizes[i] == DIM_N)           bias = (const float*)d_in[i];
    }

    probe_kernel<<<1, 256>>>((const unsigned int*)x);     // also resets globals
    amax_x_kernel<<<2048, 256>>>(x);
    amax_w_kernel<<<2048, 256>>>(w);
    quant_x_kernel<<<2048, 256>>>(x);
    quant_w_kernel<<<2048, 256>>>(w);

    cudaFuncSetAttribute(gemm_f16_kernel,
                         cudaFuncAttributeMaxDynamicSharedMemorySize, SMEM_GEMM);
    gemm_f16_kernel<<<dim3(DIM_N / BN, BATCH_M / BM, 1), 256, SMEM_GEMM>>>(bias, d_out);
}

// round 15
// speedup vs baseline: 1.9505x; 1.0227x over previous
#include <cuda_runtime.h>
#include <cuda_bf16.h>
#include <cuda_fp16.h>
#include <cstdint>
#include <cstddef>

#define DEV_INLINE __device__ __forceinline__

// ---------------- problem dims (fixed) ----------------
#define BATCH_M 8192   // 2*4096 rows of x
#define DIM_K   4096
#define DIM_N   4096

// ---------------- scratch (static device arrays; no cudaMalloc) ----------
// quantized values stored as f16 (e4m3 grid is exactly representable in f16)
__device__ __align__(16) __half g_qx_h[(size_t)BATCH_M * DIM_K]; // 64 MB
__device__ __align__(16) __half g_qw_h[(size_t)DIM_N * DIM_K];   // 32 MB
__device__ unsigned int g_amax_bits[2];   // [0]=x, [1]=w
__device__ unsigned int g_lo16_or;        // 0 => x/out are fp32 (bf16-upcast harness mode)

// ---------------- helpers ----------------
DEV_INLINE uint32_t qpair_h2(float lo, float hi) {
    uint16_t e;
    asm("cvt.rn.satfinite.e4m3x2.f32 %0, %1, %2;" : "=h"(e) : "f"(hi), "f"(lo));
    uint32_t h;
    asm("cvt.rn.f16x2.e4m3x2 %0, %1;" : "=r"(h) : "h"(e));
    return h;
}

DEV_INLINE float fmax4abs(float4 v, float m) {
    m = fmaxf(m, fabsf(v.x)); m = fmaxf(m, fabsf(v.y));
    m = fmaxf(m, fabsf(v.z)); m = fmaxf(m, fabsf(v.w));
    return m;
}

// ---------------- probe (also resets globals; single block) ----------------
__global__ void probe_kernel(const unsigned int* __restrict__ xw) {
    if (threadIdx.x == 0) {
        g_amax_bits[0] = 0u; g_amax_bits[1] = 0u; g_lo16_or = 0u;
    }
    __syncthreads();
    unsigned int v = 0;
    const size_t stride = (size_t)65536;
    for (int r = 0; r < 64; r++) v |= xw[r * stride + threadIdx.x] & 0xFFFFu;
    #pragma unroll
    for (int o = 16; o > 0; o >>= 1) v |= __shfl_xor_sync(0xffffffffu, v, o);
    if ((threadIdx.x & 31) == 0 && v) atomicOr(&g_lo16_or, v);
}

// ---------------- fused amax: |x| and |w| in one launch --------------------
// blocks [0, 2048): x (MLP=8, exactly 2 iters in f32 mode)
// blocks [2048, 3072): w (MLP=8, exactly 2 iters)
#define AX_BLOCKS 2048
#define AW_BLOCKS 1024
__global__ void amax_xw_kernel(const void* __restrict__ xv, const float* __restrict__ w) {
    float m = 0.0f;
    if (blockIdx.x < AX_BLOCKS) {
        const bool f32mode = (g_lo16_or == 0u);
        const int S = AX_BLOCKS * 256;
        const int base = blockIdx.x * 256 + threadIdx.x;
        if (f32mode) {
            const float4* p = reinterpret_cast<const float4*>(xv);
            const int n = (BATCH_M * DIM_K) / 4;           // 8388608 = 2 * 8 * S
            #pragma unroll
            for (int it = 0; it < 2; it++) {
                const int i = base + it * 8 * S;
                float4 v0 = p[i];         float4 v1 = p[i + S];
                float4 v2 = p[i + 2 * S]; float4 v3 = p[i + 3 * S];
                float4 v4 = p[i + 4 * S]; float4 v5 = p[i + 5 * S];
                float4 v6 = p[i + 6 * S]; float4 v7 = p[i + 7 * S];
                m = fmax4abs(v0, m); m = fmax4abs(v1, m);
                m = fmax4abs(v2, m); m = fmax4abs(v3, m);
                m = fmax4abs(v4, m); m = fmax4abs(v5, m);
                m = fmax4abs(v6, m); m = fmax4abs(v7, m);
            }
            (void)n;
        } else {
            const uint4* p = reinterpret_cast<const uint4*>(xv);
            const int n = (BATCH_M * DIM_K) / 8;
            for (int i = base; i < n; i += S) {
                uint4 v = p[i];
                uint32_t ws[4] = {v.x, v.y, v.z, v.w};
                #pragma unroll
                for (int j = 0; j < 4; j++) {
                    __nv_bfloat162 h2 = *reinterpret_cast<__nv_bfloat162*>(&ws[j]);
                    m = fmaxf(m, fabsf(__bfloat162float(h2.x)));
                    m = fmaxf(m, fabsf(__bfloat162float(h2.y)));
                }
            }
        }
        #pragma unroll
        for (int o = 16; o > 0; o >>= 1) m = fmaxf(m, __shfl_xor_sync(0xffffffffu, m, o));
        if ((threadIdx.x & 31) == 0) atomicMax(&g_amax_bits[0], __float_as_uint(m));
    } else {
        const int S = AW_BLOCKS * 256;
        const int base = (blockIdx.x - AX_BLOCKS) * 256 + threadIdx.x;
        const float4* p = reinterpret_cast<const float4*>(w);
        // n = 4194304 = 2 * 8 * S
        #pragma unroll
        for (int it = 0; it < 2; it++) {
            const int i = base + it * 8 * S;
            float4 v0 = p[i];         float4 v1 = p[i + S];
            float4 v2 = p[i + 2 * S]; float4 v3 = p[i + 3 * S];
            float4 v4 = p[i + 4 * S]; float4 v5 = p[i + 5 * S];
            float4 v6 = p[i + 6 * S]; float4 v7 = p[i + 7 * S];
            m = fmax4abs(v0, m); m = fmax4abs(v1, m);
            m = fmax4abs(v2, m); m = fmax4abs(v3, m);
            m = fmax4abs(v4, m); m = fmax4abs(v5, m);
            m = fmax4abs(v6, m); m = fmax4abs(v7, m);
        }
        #pragma unroll
        for (int o = 16; o > 0; o >>= 1) m = fmaxf(m, __shfl_xor_sync(0xffffffffu, m, o));
        if ((threadIdx.x & 31) == 0) atomicMax(&g_amax_bits[1], __float_as_uint(m));
    }
}

// ---------------- fused quantize: x and w -> e4m3 grid (f16) ---------------
__global__ void quant_xw_kernel(const void* __restrict__ xv, const float* __restrict__ w) {
    if (blockIdx.x < AX_BLOCKS) {
        const bool f32mode = (g_lo16_or == 0u);
        const float amax = __uint_as_float(g_amax_bits[0]);
        const float scale = 448.0f / fmaxf(amax, 1e-12f);
        const int S = AX_BLOCKS * 256;
        const int base = blockIdx.x * 256 + threadIdx.x;
        if (f32mode) {
            const float4* p = reinterpret_cast<const float4*>(xv);
            uint2* q = reinterpret_cast<uint2*>(g_qx_h);
            // n = 8388608 = 4 * 4 * S
            #pragma unroll
            for (int it = 0; it < 4; it++) {
                const int i = base + it * 4 * S;
                float4 v0 = p[i];
                float4 v1 = p[i + S];
                float4 v2 = p[i + 2 * S];
                float4 v3 = p[i + 3 * S];
                q[i]         = make_uint2(qpair_h2(v0.x * scale, v0.y * scale),
                                          qpair_h2(v0.z * scale, v0.w * scale));
                q[i + S]     = make_uint2(qpair_h2(v1.x * scale, v1.y * scale),
                                          qpair_h2(v1.z * scale, v1.w * scale));
                q[i + 2 * S] = make_uint2(qpair_h2(v2.x * scale, v2.y * scale),
                                          qpair_h2(v2.z * scale, v2.w * scale));
                q[i + 3 * S] = make_uint2(qpair_h2(v3.x * scale, v3.y * scale),
                                          qpair_h2(v3.z * scale, v3.w * scale));
            }
        } else {
            const uint4* p = reinterpret_cast<const uint4*>(xv);
            uint4* q = reinterpret_cast<uint4*>(g_qx_h);
            const int n = (BATCH_M * DIM_K) / 8;
            for (int i = base; i < n; i += S) {
                uint4 v = p[i];
                uint32_t ws[4] = {v.x, v.y, v.z, v.w};
                uint4 o;
                uint32_t* op = reinterpret_cast<uint32_t*>(&o);
                #pragma unroll
                for (int j = 0; j < 4; j++) {
                    __nv_bfloat162 h2 = *reinterpret_cast<__nv_bfloat162*>(&ws[j]);
                    op[j] = qpair_h2(__bfloat162float(h2.x) * scale,
                                     __bfloat162float(h2.y) * scale);
                }
                q[i] = o;
            }
        }
    } else {
        const float amax = __uint_as_float(g_amax_bits[1]);
        const float scale = 448.0f / fmaxf(amax, 1e-12f);
        const int S = AW_BLOCKS * 256;
        const int base = (blockIdx.x - AX_BLOCKS) * 256 + threadIdx.x;
        const float4* p = reinterpret_cast<const float4*>(w);
        uint2* q = reinterpret_cast<uint2*>(g_qw_h);
        // n = 4194304 = 4 * 4 * S
        #pragma unroll
        for (int it = 0; it < 4; it++) {
            const int i = base + it * 4 * S;
            float4 v0 = p[i];
            float4 v1 = p[i + S];
            float4 v2 = p[i + 2 * S];
            float4 v3 = p[i + 3 * S];
            q[i]         = make_uint2(qpair_h2(v0.x * scale, v0.y * scale),
                                      qpair_h2(v0.z * scale, v0.w * scale));
            q[i + S]     = make_uint2(qpair_h2(v1.x * scale, v1.y * scale),
                                      qpair_h2(v1.z * scale, v1.w * scale));
            q[i + 2 * S] = make_uint2(qpair_h2(v2.x * scale, v2.y * scale),
                                      qpair_h2(v2.z * scale, v2.w * scale));
            q[i + 3 * S] = make_uint2(qpair_h2(v3.x * scale, v3.y * scale),
                                      qpair_h2(v3.z * scale, v3.w * scale));
        }
    }
}

// ======================= GEMM: mma.sync m16n8k16 f16 + ldmatrix ============
// (unchanged from R14 — measured at ~99% of the legacy HMMA issue ceiling)

#define BM 128
#define BN 128
#define BK 64
#define GSTAGES 3
#define K_ITERS (DIM_K / BK)                     // 64
#define A_TILE_B (BM * BK * 2)                   // 16384
#define STAGE_BYTES (2 * A_TILE_B)               // 32768
#define SMEM_GEMM (GSTAGES * STAGE_BYTES)        // 98304

DEV_INLINE uint32_t swzh(uint32_t row, uint32_t byte) {
    return row * 128u + ((((byte >> 4) ^ (row & 7u)) << 4) | (byte & 15u));
}

DEV_INLINE void cp16(uint32_t dst, const void* src) {
    asm volatile("cp.async.cg.shared.global [%0], [%1], 16;" :: "r"(dst), "l"(src));
}
DEV_INLINE void cp_commit() { asm volatile("cp.async.commit_group;" ::: "memory"); }
DEV_INLINE void cp_wait1()  { asm volatile("cp.async.wait_group 1;" ::: "memory"); }
DEV_INLINE void cp_wait0()  { asm volatile("cp.async.wait_group 0;" ::: "memory"); }

DEV_INLINE void ldsm_x4(uint32_t& r0, uint32_t& r1, uint32_t& r2, uint32_t& r3, uint32_t addr) {
    asm volatile("ldmatrix.sync.aligned.m8n8.x4.shared.b16 {%0,%1,%2,%3}, [%4];"
                 : "=r"(r0), "=r"(r1), "=r"(r2), "=r"(r3) : "r"(addr));
}

DEV_INLINE void mma_f16(float* c, const uint32_t* a, const uint32_t* b) {
    asm volatile(
        "mma.sync.aligned.m16n8k16.row.col.f32.f16.f16.f32 "
        "{%0,%1,%2,%3}, {%4,%5,%6,%7}, {%8,%9}, {%0,%1,%2,%3};"
        : "+f"(c[0]), "+f"(c[1]), "+f"(c[2]), "+f"(c[3])
        : "r"(a[0]), "r"(a[1]), "r"(a[2]), "r"(a[3]), "r"(b[0]), "r"(b[1]));
}

__global__ void __launch_bounds__(256, 2)
gemm_f16_kernel(const float* __restrict__ bias, void* __restrict__ outv) {
    extern __shared__ __align__(128) char smem_raw[];
    const uint32_t smem0 = (uint32_t)__cvta_generic_to_shared(smem_raw);

    const int tid  = threadIdx.x;
    const int wid  = tid >> 5;
    const int lane = tid & 31;
    const int warpM = (wid & 1) * 64;
    const int warpN = (wid >> 1) * 32;

    const uint32_t aRowOff  = (uint32_t)((lane & 7) + ((lane >> 3) & 1) * 8);
    const uint32_t aByteOff = (uint32_t)((lane >> 4) * 16);
    const uint32_t bRowOff  = (uint32_t)((lane & 7) + (lane >> 4) * 8);
    const uint32_t bByteOff = (uint32_t)(((lane >> 3) & 1) * 16);

    const int bx = blockIdx.x;
    const int by = blockIdx.y;
    const __half* gA = g_qx_h + (size_t)by * BM * DIM_K;
    const __half* gB = g_qw_h + (size_t)bx * BN * DIM_K;

    auto load_stage = [&](int s, int kb) {
        const uint32_t base = smem0 + (uint32_t)s * STAGE_BYTES;
        const __half* aSrc = gA + (size_t)kb * BK;
        #pragma unroll
        for (int i = 0; i < 4; i++) {
            int idx = i * 256 + tid;
            uint32_t row = (uint32_t)(idx >> 3), c = (uint32_t)(idx & 7);
            cp16(base + row * 128u + ((c ^ (row & 7u)) << 4),
                 aSrc + (size_t)row * DIM_K + c * 8);
        }
        const uint32_t bbase = base + A_TILE_B;
        const __half* bSrc = gB + (size_t)kb * BK;
        #pragma unroll
        for (int i = 0; i < 4; i++) {
            int idx = i * 256 + tid;
            uint32_t row = (uint32_t)(idx >> 3), c = (uint32_t)(idx & 7);
            cp16(bbase + row * 128u + ((c ^ (row & 7u)) << 4),
                 bSrc + (size_t)row * DIM_K + c * 8);
        }
    };

    float acc[4][4][4];
    #pragma unroll
    for (int mi = 0; mi < 4; mi++)
        #pragma unroll
        for (int ni = 0; ni < 4; ni++)
            #pragma unroll
            for (int j = 0; j < 4; j++) acc[mi][ni][j] = 0.0f;

    load_stage(0, 0); cp_commit();
    load_stage(1, 1); cp_commit();

    int sC = 0;
    int sL = 2;
    for (int k = 0; k < K_ITERS; k++) {
        cp_wait1();
        __syncthreads();

        const int kn = k + 2;
        if (kn < K_ITERS) load_stage(sL, kn);
        cp_commit();

        const uint32_t aBase = smem0 + (uint32_t)sC * STAGE_BYTES;
        const uint32_t bBase = aBase + A_TILE_B;

        #pragma unroll
        for (int ks = 0; ks < 4; ks++) {
            const uint32_t kb = (uint32_t)(ks * 32);
            uint32_t af[4][4];
            uint32_t bf[4][2];
            #pragma unroll
            for (int mi = 0; mi < 4; mi++) {
                const uint32_t row = (uint32_t)(warpM + mi * 16) + aRowOff;
                ldsm_x4(af[mi][0], af[mi][1], af[mi][2], af[mi][3],
                        aBase + swzh(row, kb + aByteOff));
            }
            #pragma unroll
            for (int np = 0; np < 2; np++) {
                const uint32_t row = (uint32_t)(warpN + np * 16) + bRowOff;
                ldsm_x4(bf[2 * np][0], bf[2 * np][1], bf[2 * np + 1][0], bf[2 * np + 1][1],
                        bBase + swzh(row, kb + bByteOff));
            }
            #pragma unroll
            for (int mi = 0; mi < 4; mi++)
                #pragma unroll
                for (int ni = 0; ni < 4; ni++)
                    mma_f16(acc[mi][ni], af[mi], bf[ni]);
        }

        sC = (sC == GSTAGES - 1) ? 0 : sC + 1;
        sL = (sL == GSTAGES - 1) ? 0 : sL + 1;
    }
    cp_wait0();

    // ---------------- epilogue: scale, bf16 bias add, dual-dtype store ------
    const float ax = __uint_as_float(g_amax_bits[0]);
    const float aw = __uint_as_float(g_amax_bits[1]);
    const float sc = (1.0f / (448.0f / fmaxf(ax, 1e-12f)))
                   * (1.0f / (448.0f / fmaxf(aw, 1e-12f)));
    const bool f32out = (g_lo16_or == 0u);

    const int colQ = (lane & 3) << 1;
    __nv_bfloat16 bb[4][2];
    #pragma unroll
    for (int ni = 0; ni < 4; ni++) {
        const int col = bx * BN + warpN + ni * 8 + colQ;
        const float2 bv = *reinterpret_cast<const float2*>(bias + col);
        bb[ni][0] = __float2bfloat16(bv.x);
        bb[ni][1] = __float2bfloat16(bv.y);
    }

    #pragma unroll
    for (int mi = 0; mi < 4; mi++) {
        const size_t row0 = (size_t)(by * BM + warpM + mi * 16 + (lane >> 2));
        #pragma unroll
        for (int ni = 0; ni < 4; ni++) {
            const size_t col = (size_t)(bx * BN + warpN + ni * 8 + colQ);
            __nv_bfloat16 v00 = __hadd(__float2bfloat16(acc[mi][ni][0] * sc), bb[ni][0]);
            __nv_bfloat16 v01 = __hadd(__float2bfloat16(acc[mi][ni][1] * sc), bb[ni][1]);
            __nv_bfloat16 v10 = __hadd(__float2bfloat16(acc[mi][ni][2] * sc), bb[ni][0]);
            __nv_bfloat16 v11 = __hadd(__float2bfloat16(acc[mi][ni][3] * sc), bb[ni][1]);
            if (f32out) {
                float* outp = reinterpret_cast<float*>(outv);
                *reinterpret_cast<float2*>(outp + row0 * DIM_N + col) =
                    make_float2(__bfloat162float(v00), __bfloat162float(v01));
                *reinterpret_cast<float2*>(outp + (row0 + 8) * DIM_N + col) =
                    make_float2(__bfloat162float(v10), __bfloat162float(v11));
            } else {
                __nv_bfloat16* outp = reinterpret_cast<__nv_bfloat16*>(outv);
                __nv_bfloat162 lo = __halves2bfloat162(v00, v01);
                __nv_bfloat162 hi = __halves2bfloat162(v10, v11);
                *reinterpret_cast<uint32_t*>(outp + row0 * DIM_N + col) =
                    *reinterpret_cast<uint32_t*>(&lo);
                *reinterpret_cast<uint32_t*>(outp + (row0 + 8) * DIM_N + col) =
                    *reinterpret_cast<uint32_t*>(&hi);
            }
        }
    }
}

// ---------------- launch ----------------
extern "C" void kernel_launch(void* const* d_in, const int* in_sizes, int n_in,
                              void* d_out, int out_size) {
    const void* x = nullptr;
    const float* w = nullptr;
    const float* bias = nullptr;
    for (int i = 0; i < n_in; i++) {
        if (in_sizes[i] == BATCH_M * DIM_K)      x    = d_in[i];
        else if (in_sizes[i] == DIM_N * DIM_K)   w    = (const float*)d_in[i];
        else if (in_sizes[i] == DIM_N)           bias = (const float*)d_in[i];
    }

    probe_kernel<<<1, 256>>>((const unsigned int*)x);            // resets globals
    amax_xw_kernel<<<AX_BLOCKS + AW_BLOCKS, 256>>>(x, w);        // fused amax
    quant_xw_kernel<<<AX_BLOCKS + AW_BLOCKS, 256>>>(x, w);       // fused quant

    cudaFuncSetAttribute(gemm_f16_kernel,
                         cudaFuncAttributeMaxDynamicSharedMemorySize, SMEM_GEMM);
    gemm_f16_kernel<<<dim3(DIM_N / BN, BATCH_M / BM, 1), 256, SMEM_GEMM>>>(bias, d_out);
}

// round 17
// speedup vs baseline: 1.9816x; 1.0160x over previous
#include <cuda_runtime.h>
#include <cuda_bf16.h>
#include <cuda_fp16.h>
#include <cstdint>
#include <cstddef>

#define DEV_INLINE __device__ __forceinline__

// ---------------- problem dims (fixed) ----------------
#define BATCH_M 8192   // 2*4096 rows of x
#define DIM_K   4096
#define DIM_N   4096

// ---------------- scratch (static device arrays; no cudaMalloc) ----------
__device__ __align__(16) __half g_qx_h[(size_t)BATCH_M * DIM_K]; // 64 MB
__device__ __align__(16) __half g_qw_h[(size_t)DIM_N * DIM_K];   // 32 MB
__device__ unsigned int g_amax_bits[2];   // [0]=x, [1]=w
__device__ unsigned int g_lo16_or;        // 0 => x/out are fp32 (bf16-upcast harness mode)

// ---------------- helpers ----------------
DEV_INLINE uint32_t qpair_h2(float lo, float hi) {
    uint16_t e;
    asm("cvt.rn.satfinite.e4m3x2.f32 %0, %1, %2;" : "=h"(e) : "f"(hi), "f"(lo));
    uint32_t h;
    asm("cvt.rn.f16x2.e4m3x2 %0, %1;" : "=r"(h) : "h"(e));
    return h;
}

DEV_INLINE float fmax4abs(float4 v, float m) {
    m = fmaxf(m, fabsf(v.x)); m = fmaxf(m, fabsf(v.y));
    m = fmaxf(m, fabsf(v.z)); m = fmaxf(m, fabsf(v.w));
    return m;
}

// ---------------- probe (also resets globals; single block) ----------------
__global__ void probe_kernel(const unsigned int* __restrict__ xw) {
    if (threadIdx.x == 0) {
        g_amax_bits[0] = 0u; g_amax_bits[1] = 0u; g_lo16_or = 0u;
    }
    __syncthreads();
    unsigned int v = 0;
    const size_t stride = (size_t)65536;
    for (int r = 0; r < 64; r++) v |= xw[r * stride + threadIdx.x] & 0xFFFFu;
    #pragma unroll
    for (int o = 16; o > 0; o >>= 1) v |= __shfl_xor_sync(0xffffffffu, v, o);
    if ((threadIdx.x & 31) == 0 && v) atomicOr(&g_lo16_or, v);
}

// ---------------- fused amax: |x| and |w| in one launch --------------------
#define AX_BLOCKS 2048
#define AW_BLOCKS 1024
__global__ void amax_xw_kernel(const void* __restrict__ xv, const float* __restrict__ w) {
    float m = 0.0f;
    if (blockIdx.x < AX_BLOCKS) {
        const bool f32mode = (g_lo16_or == 0u);
        const int S = AX_BLOCKS * 256;
        const int base = blockIdx.x * 256 + threadIdx.x;
        if (f32mode) {
            const float4* p = reinterpret_cast<const float4*>(xv);
            #pragma unroll
            for (int it = 0; it < 2; it++) {
                const int i = base + it * 8 * S;
                float4 v0 = p[i];         float4 v1 = p[i + S];
                float4 v2 = p[i + 2 * S]; float4 v3 = p[i + 3 * S];
                float4 v4 = p[i + 4 * S]; float4 v5 = p[i + 5 * S];
                float4 v6 = p[i + 6 * S]; float4 v7 = p[i + 7 * S];
                m = fmax4abs(v0, m); m = fmax4abs(v1, m);
                m = fmax4abs(v2, m); m = fmax4abs(v3, m);
                m = fmax4abs(v4, m); m = fmax4abs(v5, m);
                m = fmax4abs(v6, m); m = fmax4abs(v7, m);
            }
        } else {
            const uint4* p = reinterpret_cast<const uint4*>(xv);
            const int n = (BATCH_M * DIM_K) / 8;
            for (int i = base; i < n; i += S) {
                uint4 v = p[i];
                uint32_t ws[4] = {v.x, v.y, v.z, v.w};
                #pragma unroll
                for (int j = 0; j < 4; j++) {
                    __nv_bfloat162 h2 = *reinterpret_cast<__nv_bfloat162*>(&ws[j]);
                    m = fmaxf(m, fabsf(__bfloat162float(h2.x)));
                    m = fmaxf(m, fabsf(__bfloat162float(h2.y)));
                }
            }
        }
        #pragma unroll
        for (int o = 16; o > 0; o >>= 1) m = fmaxf(m, __shfl_xor_sync(0xffffffffu, m, o));
        if ((threadIdx.x & 31) == 0) atomicMax(&g_amax_bits[0], __float_as_uint(m));
    } else {
        const int S = AW_BLOCKS * 256;
        const int base = (blockIdx.x - AX_BLOCKS) * 256 + threadIdx.x;
        const float4* p = reinterpret_cast<const float4*>(w);
        #pragma unroll
        for (int it = 0; it < 2; it++) {
            const int i = base + it * 8 * S;
            float4 v0 = p[i];         float4 v1 = p[i + S];
            float4 v2 = p[i + 2 * S]; float4 v3 = p[i + 3 * S];
            float4 v4 = p[i + 4 * S]; float4 v5 = p[i + 5 * S];
            float4 v6 = p[i + 6 * S]; float4 v7 = p[i + 7 * S];
            m = fmax4abs(v0, m); m = fmax4abs(v1, m);
            m = fmax4abs(v2, m); m = fmax4abs(v3, m);
            m = fmax4abs(v4, m); m = fmax4abs(v5, m);
            m = fmax4abs(v6, m); m = fmax4abs(v7, m);
        }
        #pragma unroll
        for (int o = 16; o > 0; o >>= 1) m = fmaxf(m, __shfl_xor_sync(0xffffffffu, m, o));
        if ((threadIdx.x & 31) == 0) atomicMax(&g_amax_bits[1], __float_as_uint(m));
    }
}

// ---------------- fused quantize: x and w -> e4m3 grid (f16) ---------------
__global__ void quant_xw_kernel(const void* __restrict__ xv, const float* __restrict__ w) {
    if (blockIdx.x < AX_BLOCKS) {
        const bool f32mode = (g_lo16_or == 0u);
        const float amax = __uint_as_float(g_amax_bits[0]);
        const float scale = 448.0f / fmaxf(amax, 1e-12f);
        const int S = AX_BLOCKS * 256;
        const int base = blockIdx.x * 256 + threadIdx.x;
        if (f32mode) {
            const float4* p = reinterpret_cast<const float4*>(xv);
            uint2* q = reinterpret_cast<uint2*>(g_qx_h);
            #pragma unroll
            for (int it = 0; it < 4; it++) {
                const int i = base + it * 4 * S;
                float4 v0 = p[i];
                float4 v1 = p[i + S];
                float4 v2 = p[i + 2 * S];
                float4 v3 = p[i + 3 * S];
                q[i]         = make_uint2(qpair_h2(v0.x * scale, v0.y * scale),
                                          qpair_h2(v0.z * scale, v0.w * scale));
                q[i + S]     = make_uint2(qpair_h2(v1.x * scale, v1.y * scale),
                                          qpair_h2(v1.z * scale, v1.w * scale));
                q[i + 2 * S] = make_uint2(qpair_h2(v2.x * scale, v2.y * scale),
                                          qpair_h2(v2.z * scale, v2.w * scale));
                q[i + 3 * S] = make_uint2(qpair_h2(v3.x * scale, v3.y * scale),
                                          qpair_h2(v3.z * scale, v3.w * scale));
            }
        } else {
            const uint4* p = reinterpret_cast<const uint4*>(xv);
            uint4* q = reinterpret_cast<uint4*>(g_qx_h);
            const int n = (BATCH_M * DIM_K) / 8;
            for (int i = base; i < n; i += S) {
                uint4 v = p[i];
                uint32_t ws[4] = {v.x, v.y, v.z, v.w};
                uint4 o;
                uint32_t* op = reinterpret_cast<uint32_t*>(&o);
                #pragma unroll
                for (int j = 0; j < 4; j++) {
                    __nv_bfloat162 h2 = *reinterpret_cast<__nv_bfloat162*>(&ws[j]);
                    op[j] = qpair_h2(__bfloat162float(h2.x) * scale,
                                     __bfloat162float(h2.y) * scale);
                }
                q[i] = o;
            }
        }
    } else {
        const float amax = __uint_as_float(g_amax_bits[1]);
        const float scale = 448.0f / fmaxf(amax, 1e-12f);
        const int S = AW_BLOCKS * 256;
        const int base = (blockIdx.x - AX_BLOCKS) * 256 + threadIdx.x;
        const float4* p = reinterpret_cast<const float4*>(w);
        uint2* q = reinterpret_cast<uint2*>(g_qw_h);
        #pragma unroll
        for (int it = 0; it < 4; it++) {
            const int i = base + it * 4 * S;
            float4 v0 = p[i];
            float4 v1 = p[i + S];
            float4 v2 = p[i + 2 * S];
            float4 v3 = p[i + 3 * S];
            q[i]         = make_uint2(qpair_h2(v0.x * scale, v0.y * scale),
                                      qpair_h2(v0.z * scale, v0.w * scale));
            q[i + S]     = make_uint2(qpair_h2(v1.x * scale, v1.y * scale),
                                      qpair_h2(v1.z * scale, v1.w * scale));
            q[i + 2 * S] = make_uint2(qpair_h2(v2.x * scale, v2.y * scale),
                                      qpair_h2(v2.z * scale, v2.w * scale));
            q[i + 3 * S] = make_uint2(qpair_h2(v3.x * scale, v3.y * scale),
                                      qpair_h2(v3.z * scale, v3.w * scale));
        }
    }
}

// ======================= GEMM: mma.sync m16n8k16 f16 + ldmatrix ============
// full/empty mbarrier pipeline; full is DMA-driven via cp.async.mbarrier.arrive.

#define BM 128
#define BN 128
#define BK 64
#define GSTAGES 3
#define K_ITERS (DIM_K / BK)                     // 64
#define A_TILE_B (BM * BK * 2)                   // 16384
#define STAGE_BYTES (2 * A_TILE_B)               // 32768
#define CTRL_BYTES 1024                          // mbarriers live here
#define SMEM_GEMM (CTRL_BYTES + GSTAGES * STAGE_BYTES)   // 99328

DEV_INLINE uint32_t swzh(uint32_t row, uint32_t byte) {
    return row * 128u + ((((byte >> 4) ^ (row & 7u)) << 4) | (byte & 15u));
}

DEV_INLINE void cp16(uint32_t dst, const void* src) {
    asm volatile("cp.async.cg.shared.global [%0], [%1], 16;" :: "r"(dst), "l"(src));
}
DEV_INLINE void mbar_init(uint32_t addr, uint32_t count) {
    asm volatile("mbarrier.init.shared.b64 [%0], %1;" :: "r"(addr), "r"(count) : "memory");
}
// arrive fires when ALL this thread's prior cp.asyncs have completed; .noinc
// counts against the initialized expected-arrival count (256 = all threads).
DEV_INLINE void cpasync_mbar_arrive(uint32_t addr) {
    asm volatile("cp.async.mbarrier.arrive.noinc.shared.b64 [%0];" :: "r"(addr) : "memory");
}
DEV_INLINE void mbar_arrive(uint32_t addr) {
    asm volatile("{\n\t.reg .b64 t;\n\tmbarrier.arrive.shared.b64 t, [%0];\n\t}"
                 :: "r"(addr) : "memory");
}
DEV_INLINE void mbar_wait(uint32_t addr, uint32_t phase) {
    asm volatile(
        "{\n\t.reg .pred P;\n"
        "WL%=:\n\t"
        "mbarrier.try_wait.parity.acquire.cta.shared::cta.b64 P, [%0], %1, 0x989680;\n\t"
        "@P bra WD%=;\n\t"
        "bra WL%=;\n"
        "WD%=:\n\t}"
        :: "r"(addr), "r"(phase) : "memory");
}

DEV_INLINE void ldsm_x4(uint32_t& r0, uint32_t& r1, uint32_t& r2, uint32_t& r3, uint32_t addr) {
    asm volatile("ldmatrix.sync.aligned.m8n8.x4.shared.b16 {%0,%1,%2,%3}, [%4];"
                 : "=r"(r0), "=r"(r1), "=r"(r2), "=r"(r3) : "r"(addr));
}

DEV_INLINE void mma_f16(float* c, const uint32_t* a, const uint32_t* b) {
    asm volatile(
        "mma.sync.aligned.m16n8k16.row.col.f32.f16.f16.f32 "
        "{%0,%1,%2,%3}, {%4,%5,%6,%7}, {%8,%9}, {%0,%1,%2,%3};"
        : "+f"(c[0]), "+f"(c[1]), "+f"(c[2]), "+f"(c[3])
        : "r"(a[0]), "r"(a[1]), "r"(a[2]), "r"(a[3]), "r"(b[0]), "r"(b[1]));
}

__global__ void __launch_bounds__(256, 2)
gemm_f16_kernel(const float* __restrict__ bias, void* __restrict__ outv) {
    extern __shared__ __align__(128) char smem_raw[];
    const uint32_t smem0  = (uint32_t)__cvta_generic_to_shared(smem_raw);
    const uint32_t stage0 = smem0 + CTRL_BYTES;
    // barrier layout: full[s] at smem0 + 8*s ; empty[s] at smem0 + 64 + 8*s

    const int tid  = threadIdx.x;
    const int wid  = tid >> 5;
    const int lane = tid & 31;
    const int warpM = (wid & 1) * 64;
    const int warpN = (wid >> 1) * 32;

    const uint32_t aRowOff  = (uint32_t)((lane & 7) + ((lane >> 3) & 1) * 8);
    const uint32_t aByteOff = (uint32_t)((lane >> 4) * 16);
    const uint32_t bRowOff  = (uint32_t)((lane & 7) + (lane >> 4) * 8);
    const uint32_t bByteOff = (uint32_t)(((lane >> 3) & 1) * 16);

    const int bx = blockIdx.x;
    const int by = blockIdx.y;
    const __half* gA = g_qx_h + (size_t)by * BM * DIM_K;
    const __half* gB = g_qw_h + (size_t)bx * BN * DIM_K;

    auto load_stage = [&](int s, int kb) {
        const uint32_t base = stage0 + (uint32_t)s * STAGE_BYTES;
        const __half* aSrc = gA + (size_t)kb * BK;
        #pragma unroll
        for (int i = 0; i < 4; i++) {
            int idx = i * 256 + tid;
            uint32_t row = (uint32_t)(idx >> 3), c = (uint32_t)(idx & 7);
            cp16(base + row * 128u + ((c ^ (row & 7u)) << 4),
                 aSrc + (size_t)row * DIM_K + c * 8);
        }
        const uint32_t bbase = base + A_TILE_B;
        const __half* bSrc = gB + (size_t)kb * BK;
        #pragma unroll
        for (int i = 0; i < 4; i++) {
            int idx = i * 256 + tid;
            uint32_t row = (uint32_t)(idx >> 3), c = (uint32_t)(idx & 7);
            cp16(bbase + row * 128u + ((c ^ (row & 7u)) << 4),
                 bSrc + (size_t)row * DIM_K + c * 8);
        }
    };

    // init full/empty mbarriers (expected arrivals = all 256 threads)
    if (tid == 0) {
        #pragma unroll
        for (int s = 0; s < GSTAGES; s++) {
            mbar_init(smem0 + 8u * s, 256u);         // full[s]
            mbar_init(smem0 + 64u + 8u * s, 256u);   // empty[s]
        }
    }
    __syncthreads();   // one-time: barrier visibility before any use

    float acc[4][4][4];
    #pragma unroll
    for (int mi = 0; mi < 4; mi++)
        #pragma unroll
        for (int ni = 0; ni < 4; ni++)
            #pragma unroll
            for (int j = 0; j < 4; j++) acc[mi][ni][j] = 0.0f;

    // prologue: fill stages 0,1; full arrives fire on DMA completion
    load_stage(0, 0); cpasync_mbar_arrive(smem0 + 0u);
    load_stage(1, 1); cpasync_mbar_arrive(smem0 + 8u);

    int sC = 0;
    int sL = 2;
    for (int k = 0; k < K_ITERS; k++) {
        // chunk-k resident (DMA-completion driven; no warp rendezvous)
        mbar_wait(smem0 + 8u * (uint32_t)sC, (uint32_t)((k / 3) & 1));

        const uint32_t aBase = stage0 + (uint32_t)sC * STAGE_BYTES;
        const uint32_t bBase = aBase + A_TILE_B;

        #pragma unroll
        for (int ks = 0; ks < 4; ks++) {
            const uint32_t kb = (uint32_t)(ks * 32);
            uint32_t af[4][4];
            uint32_t bf[4][2];
            #pragma unroll
            for (int mi = 0; mi < 4; mi++) {
                const uint32_t row = (uint32_t)(warpM + mi * 16) + aRowOff;
                ldsm_x4(af[mi][0], af[mi][1], af[mi][2], af[mi][3],
                        aBase + swzh(row, kb + aByteOff));
            }
            #pragma unroll
            for (int np = 0; np < 2; np++) {
                const uint32_t row = (uint32_t)(warpN + np * 16) + bRowOff;
                ldsm_x4(bf[2 * np][0], bf[2 * np][1], bf[2 * np + 1][0], bf[2 * np + 1][1],
                        bBase + swzh(row, kb + bByteOff));
            }
            #pragma unroll
            for (int mi = 0; mi < 4; mi++)
                #pragma unroll
                for (int ni = 0; ni < 4; ni++)
                    mma_f16(acc[mi][ni], af[mi], bf[ni]);
        }
        // MMAs consumed all fragments -> ldsm smem reads of stage sC complete
        mbar_arrive(smem0 + 64u + 8u * (uint32_t)sC);

        const int kn = k + 2;
        if (kn < K_ITERS) {
            if (k >= 1) {
                // previous readers of stage sL (iteration k-1) must be done
                mbar_wait(smem0 + 64u + 8u * (uint32_t)sL, (uint32_t)(((k - 1) / 3) & 1));
            }
            load_stage(sL, kn);
            cpasync_mbar_arrive(smem0 + 8u * (uint32_t)sL);
        }

        sC = (sC == GSTAGES - 1) ? 0 : sC + 1;
        sL = (sL == GSTAGES - 1) ? 0 : sL + 1;
    }

    // ---------------- epilogue: scale, bf16 bias add, dual-dtype store ------
    const float ax = __uint_as_float(g_amax_bits[0]);
    const float aw = __uint_as_float(g_amax_bits[1]);
    const float sc = (1.0f / (448.0f / fmaxf(ax, 1e-12f)))
                   * (1.0f / (448.0f / fmaxf(aw, 1e-12f)));
    const bool f32out = (g_lo16_or == 0u);

    const int colQ = (lane & 3) << 1;
    __nv_bfloat16 bb[4][2];
    #pragma unroll
    for (int ni = 0; ni < 4; ni++) {
        const int col = bx * BN + warpN + ni * 8 + colQ;
        const float2 bv = *reinterpret_cast<const float2*>(bias + col);
        bb[ni][0] = __float2bfloat16(bv.x);
        bb[ni][1] = __float2bfloat16(bv.y);
    }

    #pragma unroll
    for (int mi = 0; mi < 4; mi++) {
        const size_t row0 = (size_t)(by * BM + warpM + mi * 16 + (lane >> 2));
        #pragma unroll
        for (int ni = 0; ni < 4; ni++) {
            const size_t col = (size_t)(bx * BN + warpN + ni * 8 + colQ);
            __nv_bfloat16 v00 = __hadd(__float2bfloat16(acc[mi][ni][0] * sc), bb[ni][0]);
            __nv_bfloat16 v01 = __hadd(__float2bfloat16(acc[mi][ni][1] * sc), bb[ni][1]);
            __nv_bfloat16 v10 = __hadd(__float2bfloat16(acc[mi][ni][2] * sc), bb[ni][0]);
            __nv_bfloat16 v11 = __hadd(__float2bfloat16(acc[mi][ni][3] * sc), bb[ni][1]);
            if (f32out) {
                float* outp = reinterpret_cast<float*>(outv);
                *reinterpret_cast<float2*>(outp + row0 * DIM_N + col) =
                    make_float2(__bfloat162float(v00), __bfloat162float(v01));
                *reinterpret_cast<float2*>(outp + (row0 + 8) * DIM_N + col) =
                    make_float2(__bfloat162float(v10), __bfloat162float(v11));
            } else {
                __nv_bfloat16* outp = reinterpret_cast<__nv_bfloat16*>(outv);
                __nv_bfloat162 lo = __halves2bfloat162(v00, v01);
                __nv_bfloat162 hi = __halves2bfloat162(v10, v11);
                *reinterpret_cast<uint32_t*>(outp + row0 * DIM_N + col) =
                    *reinterpret_cast<uint32_t*>(&lo);
                *reinterpret_cast<uint32_t*>(outp + (row0 + 8) * DIM_N + col) =
                    *reinterpret_cast<uint32_t*>(&hi);
            }
        }
    }
}

// ---------------- launch ----------------
extern "C" void kernel_launch(void* const* d_in, const int* in_sizes, int n_in,
                              void* d_out, int out_size) {
    const void* x = nullptr;
    const float* w = nullptr;
    const float* bias = nullptr;
    for (int i = 0; i < n_in; i++) {
        if (in_sizes[i] == BATCH_M * DIM_K)      x    = d_in[i];
        else if (in_sizes[i] == DIM_N * DIM_K)   w    = (const float*)d_in[i];
        else if (in_sizes[i] == DIM_N)           bias = (const float*)d_in[i];
    }

    probe_kernel<<<1, 256>>>((const unsigned int*)x);            // resets globals
    amax_xw_kernel<<<AX_BLOCKS + AW_BLOCKS, 256>>>(x, w);        // fused amax
    quant_xw_kernel<<<AX_BLOCKS + AW_BLOCKS, 256>>>(x, w);       // fused quant

    cudaFuncSetAttribute(gemm_f16_kernel,
                         cudaFuncAttributeMaxDynamicSharedMemorySize, SMEM_GEMM);
    gemm_f16_kernel<<<dim3(DIM_N / BN, BATCH_M / BM, 1), 256, SMEM_GEMM>>>(bias, d_out);
}